// round 7
// baseline (speedup 1.0000x reference)
#include <cuda_runtime.h>
#include <cuda_fp16.h>
#include <cstdint>

#define B_ 8
#define N_ 1024
#define D_ 768
#define H_ 12
#define HD_ 64

// Scratch (allocation-free rule: __device__ globals) — fp16 intermediates
__device__ __half g_q[B_ * H_ * N_ * HD_];       // pre-scaled by D^-0.5 * log2e
__device__ __half g_k[B_ * H_ * N_ * HD_];
__device__ __half g_v[B_ * H_ * N_ * HD_];
__device__ __half g_att[B_ * N_ * D_];           // concat layout [B*N, D]
__device__ uint32_t g_wqkv[3 * H_ * 64 * 32];    // [m][h][e][d2] half2, transposed
__device__ uint32_t g_wo[D_ * (D_ / 2)];         // [c][k2] half2

// ---------------------------------------------------------------------------
// helpers
// ---------------------------------------------------------------------------
__device__ __forceinline__ float ex2f(float x) {
    float y;
    asm("ex2.approx.ftz.f32 %0, %1;" : "=f"(y) : "f"(x));
    return y;
}

__device__ __forceinline__ uint32_t h2ex2(uint32_t a) {
    uint32_t d;
    asm("ex2.approx.f16x2 %0, %1;" : "=r"(d) : "r"(a));
    return d;
}

__device__ __forceinline__ void mma_f16(float c[4],
                                        uint32_t a0, uint32_t a1, uint32_t a2, uint32_t a3,
                                        uint32_t b0, uint32_t b1) {
    asm volatile(
        "mma.sync.aligned.m16n8k16.row.col.f32.f16.f16.f32 "
        "{%0,%1,%2,%3},{%4,%5,%6,%7},{%8,%9},{%0,%1,%2,%3};\n"
        : "+f"(c[0]), "+f"(c[1]), "+f"(c[2]), "+f"(c[3])
        : "r"(a0), "r"(a1), "r"(a2), "r"(a3), "r"(b0), "r"(b1));
}

__device__ __forceinline__ uint32_t packh2(float lo, float hi) {
    __half2 h = __floats2half2_rn(lo, hi);
    return *(uint32_t*)&h;
}

__device__ __forceinline__ void ldsm_x4(uint32_t& r0, uint32_t& r1, uint32_t& r2, uint32_t& r3,
                                        uint32_t addr) {
    asm volatile("ldmatrix.sync.aligned.m8n8.x4.shared.b16 {%0,%1,%2,%3}, [%4];"
                 : "=r"(r0), "=r"(r1), "=r"(r2), "=r"(r3) : "r"(addr));
}

__device__ __forceinline__ void ldsm_x4_t(uint32_t& r0, uint32_t& r1, uint32_t& r2, uint32_t& r3,
                                          uint32_t addr) {
    asm volatile("ldmatrix.sync.aligned.m8n8.x4.trans.shared.b16 {%0,%1,%2,%3}, [%4];"
                 : "=r"(r0), "=r"(r1), "=r"(r2), "=r"(r3) : "r"(addr));
}

__device__ __forceinline__ void cpa16(uint32_t saddr, const void* g) {
    asm volatile("cp.async.cg.shared.global [%0], [%1], 16;" :: "r"(saddr), "l"(g));
}
__device__ __forceinline__ void cpa_commit() { asm volatile("cp.async.commit_group;"); }
__device__ __forceinline__ void cpa_wait0()  { asm volatile("cp.async.wait_group 0;"); }

// ---------------------------------------------------------------------------
// Prep kernels: pack weights to fp16 once per launch.
// ---------------------------------------------------------------------------
__global__ __launch_bounds__(256) void pack_wqkv_kernel(
    const float* __restrict__ Wq, const float* __restrict__ Wk, const float* __restrict__ Wv)
{
    int idx = blockIdx.x * 256 + threadIdx.x;          // [m][h][e][d2]
    if (idx >= 3 * H_ * 64 * 32) return;
    int d2 = idx & 31;
    int e  = (idx >> 5) & 63;
    int h  = (idx >> 11) % H_;
    int m  = idx / (H_ * 64 * 32);
    const float* W = (m == 0 ? Wq : (m == 1 ? Wk : Wv)) + h * HD_ * HD_;
    g_wqkv[idx] = packh2(W[(2 * d2) * 64 + e], W[(2 * d2 + 1) * 64 + e]);
}

__global__ __launch_bounds__(256) void pack_wo_kernel(const float* __restrict__ Wo)
{
    int idx = blockIdx.x * 256 + threadIdx.x;          // [c][k2]
    if (idx >= D_ * (D_ / 2)) return;
    float2 v = *(const float2*)&Wo[2 * idx];
    g_wo[idx] = packh2(v.x, v.y);
}

// ---------------------------------------------------------------------------
// Kernel 1: per-head QKV projection (as R6).
// ---------------------------------------------------------------------------
__global__ __launch_bounds__(256) void qkv_mma_kernel(
    const float* __restrict__ x,
    const float* __restrict__ bq, const float* __restrict__ bk, const float* __restrict__ bv)
{
    extern __shared__ __align__(16) uint32_t smu[];
    uint32_t* Xs = smu;              // [128][36]
    uint32_t* Wsm = Xs + 128 * 36;   // 3 x [64][36]

    const int bh = blockIdx.y;
    const int h  = bh % H_;
    const int b  = bh / H_;
    const int n0 = blockIdx.x * 128;
    const int t  = threadIdx.x;
    const int w  = t >> 5;
    const int lane = t & 31;
    const int g  = lane >> 2;
    const int qd = lane & 3;
    const int row0 = w * 16 + g;

    const uint32_t Xs_a = (uint32_t)__cvta_generic_to_shared(Xs);
    const uint32_t Ws_a = (uint32_t)__cvta_generic_to_shared(Wsm);

#pragma unroll
    for (int i = t; i < 128 * 8; i += 256) {
        int r = i >> 3, c8 = (i & 7) << 3;
        const float* src = &x[(b * N_ + n0 + r) * D_ + h * HD_ + c8];
        float4 v0 = *(const float4*)src;
        float4 v1 = *(const float4*)(src + 4);
        uint4 pk;
        pk.x = packh2(v0.x, v0.y); pk.y = packh2(v0.z, v0.w);
        pk.z = packh2(v1.x, v1.y); pk.w = packh2(v1.z, v1.w);
        *(uint4*)&Xs[r * 36 + ((i & 7) << 2)] = pk;
    }
#pragma unroll
    for (int i = t; i < 3 * 512; i += 256) {
        int m = i >> 9, j = i & 511;
        int r = j >> 3, c = (j & 7) << 2;
        *(uint4*)&Wsm[m * 64 * 36 + r * 36 + c] =
            *(const uint4*)&g_wqkv[(m * H_ + h) * 64 * 32 + r * 32 + c];
    }
    __syncthreads();

    uint32_t xa[4][4];
    {
        const uint32_t aoff = ((w * 16 + (lane & 15)) * 36 + (lane >> 4) * 4) * 4;
#pragma unroll
        for (int kc = 0; kc < 4; kc++)
            ldsm_x4(xa[kc][0], xa[kc][1], xa[kc][2], xa[kc][3], Xs_a + aoff + kc * 32);
    }

    const float* bm[3] = {bq, bk, bv};
    __half*      om[3] = {g_q, g_k, g_v};
    const float qscale = rsqrtf((float)D_) * 1.4426950408889634f;  // full-dim quirk * log2e

    const int mB = lane >> 3, rB = lane & 7;

#pragma unroll
    for (int m = 0; m < 3; m++) {
        const float* bias = bm[m] + h * HD_;
        float acc[8][4];
#pragma unroll
        for (int nt = 0; nt < 8; nt++) {
            float bb0 = bias[nt * 8 + 2 * qd];
            float bb1 = bias[nt * 8 + 2 * qd + 1];
            acc[nt][0] = bb0; acc[nt][1] = bb1; acc[nt][2] = bb0; acc[nt][3] = bb1;
        }

        const uint32_t wbase = Ws_a + m * 64 * 36 * 4;
#pragma unroll
        for (int kc = 0; kc < 4; kc++) {
#pragma unroll
            for (int c = 0; c < 4; c++) {
                uint32_t b0, b1, b2, b3;
                uint32_t addr = wbase +
                    (((2 * c + (mB >> 1)) * 8 + rB) * 36 + kc * 8 + (mB & 1) * 4) * 4;
                ldsm_x4(b0, b1, b2, b3, addr);
                mma_f16(acc[2 * c],     xa[kc][0], xa[kc][1], xa[kc][2], xa[kc][3], b0, b1);
                mma_f16(acc[2 * c + 1], xa[kc][0], xa[kc][1], xa[kc][2], xa[kc][3], b2, b3);
            }
        }

        const float sc = (m == 0) ? qscale : 1.0f;
        __half* o = om[m] + ((size_t)bh * N_ + n0) * HD_;
#pragma unroll
        for (int nt = 0; nt < 8; nt++) {
            *(uint32_t*)&o[(row0)     * HD_ + nt * 8 + 2 * qd] = packh2(acc[nt][0] * sc, acc[nt][1] * sc);
            *(uint32_t*)&o[(row0 + 8) * HD_ + nt * 8 + 2 * qd] = packh2(acc[nt][2] * sc, acc[nt][3] * sc);
        }
    }
}

// ---------------------------------------------------------------------------
// Kernel 2: flash attention. cp.async double-buffered K/V (1 sync/tile),
// f16x2 ex2 producing packed P directly, row-sum via MMA with ones-B.
// grid (8, 96). block 256 = 8 warps.
// ---------------------------------------------------------------------------
__global__ __launch_bounds__(256, 2) void attn_mma_kernel()
{
    extern __shared__ __align__(16) uint32_t smu[];
    uint32_t* Qs = smu;                       // [128][36]
    uint32_t* Kb[2] = { Qs + 128 * 36,  Qs + 128 * 36 + 2 * 64 * 36 };
    uint32_t* Vb[2] = { Qs + 128 * 36 + 64 * 36, Qs + 128 * 36 + 3 * 64 * 36 };

    const int bh = blockIdx.y;
    const int h  = bh % H_;
    const int b  = bh / H_;
    const int q0 = blockIdx.x * 128;
    const int t  = threadIdx.x;
    const int w  = t >> 5;
    const int lane = t & 31;
    const int g  = lane >> 2;
    const int qd = lane & 3;
    const int row0 = w * 16 + g;
    const uint32_t ONE2 = 0x3C003C00u;        // half2(1,1)

    const uint32_t Qs_a = (uint32_t)__cvta_generic_to_shared(Qs);
    const uint32_t Kb_a[2] = { (uint32_t)__cvta_generic_to_shared(Kb[0]),
                               (uint32_t)__cvta_generic_to_shared(Kb[1]) };
    const uint32_t Vb_a[2] = { (uint32_t)__cvta_generic_to_shared(Vb[0]),
                               (uint32_t)__cvta_generic_to_shared(Vb[1]) };

    const uint32_t* Qg2 = (const uint32_t*)(g_q + ((size_t)bh * N_ + q0) * HD_);
    const uint32_t* Kg2 = (const uint32_t*)(g_k + (size_t)bh * N_ * HD_);
    const uint32_t* Vg2 = (const uint32_t*)(g_v + (size_t)bh * N_ * HD_);

    const int rA = t >> 3, cA = (t & 7) << 2;        // chunk t
    const int rB2 = (t + 256) >> 3, cB2 = ((t + 256) & 7) << 2;  // chunk t+256

    // issue K0/V0 via cp.async (overlaps with Q load)
    cpa16(Kb_a[0] + (rA * 36 + cA) * 4,   Kg2 + rA * 32 + cA);
    cpa16(Kb_a[0] + (rB2 * 36 + cB2) * 4, Kg2 + rB2 * 32 + cB2);
    cpa16(Vb_a[0] + (rA * 36 + cA) * 4,   Vg2 + rA * 32 + cA);
    cpa16(Vb_a[0] + (rB2 * 36 + cB2) * 4, Vg2 + rB2 * 32 + cB2);
    cpa_commit();

    // Q tile
#pragma unroll
    for (int i = t; i < 128 * 8; i += 256) {
        int r = i >> 3, c = (i & 7) << 2;
        *(uint4*)&Qs[r * 36 + c] = *(const uint4*)&Qg2[r * 32 + c];
    }
    cpa_wait0();
    __syncthreads();

    // hoist Q fragments
    uint32_t qa[4][4];
    {
        const uint32_t aoff = ((w * 16 + (lane & 15)) * 36 + (lane >> 4) * 4) * 4;
#pragma unroll
        for (int kc = 0; kc < 4; kc++)
            ldsm_x4(qa[kc][0], qa[kc][1], qa[kc][2], qa[kc][3], Qs_a + aoff + kc * 32);
    }

    const int mB = lane >> 3, rBq = lane & 7;

    float O[8][4];
#pragma unroll
    for (int dt = 0; dt < 8; dt++)
#pragma unroll
        for (int j = 0; j < 4; j++) O[dt][j] = 0.f;
    float L[4] = {0.f, 0.f, 0.f, 0.f};
    float m0 = -1e30f, m1 = -1e30f;

    for (int kt = 0; kt < N_ / 64; kt++) {
        const int cur = kt & 1;
        const bool more = (kt + 1 < N_ / 64);

        // issue next tile's loads (into the other buffer)
        if (more) {
            const uint32_t* Kn = Kg2 + (size_t)(kt + 1) * 2048;
            const uint32_t* Vn = Vg2 + (size_t)(kt + 1) * 2048;
            const int nxt = cur ^ 1;
            cpa16(Kb_a[nxt] + (rA * 36 + cA) * 4,   Kn + rA * 32 + cA);
            cpa16(Kb_a[nxt] + (rB2 * 36 + cB2) * 4, Kn + rB2 * 32 + cB2);
            cpa16(Vb_a[nxt] + (rA * 36 + cA) * 4,   Vn + rA * 32 + cA);
            cpa16(Vb_a[nxt] + (rB2 * 36 + cB2) * 4, Vn + rB2 * 32 + cB2);
            cpa_commit();
        }

        // ---- S = Q K^T ----
        float S[8][4];
#pragma unroll
        for (int nt = 0; nt < 8; nt++)
#pragma unroll
            for (int j = 0; j < 4; j++) S[nt][j] = 0.f;

#pragma unroll
        for (int kc = 0; kc < 4; kc++) {
#pragma unroll
            for (int c = 0; c < 4; c++) {
                uint32_t b0, b1, b2, b3;
                uint32_t addr = Kb_a[cur] +
                    (((2 * c + (mB >> 1)) * 8 + rBq) * 36 + kc * 8 + (mB & 1) * 4) * 4;
                ldsm_x4(b0, b1, b2, b3, addr);
                mma_f16(S[2 * c],     qa[kc][0], qa[kc][1], qa[kc][2], qa[kc][3], b0, b1);
                mma_f16(S[2 * c + 1], qa[kc][0], qa[kc][1], qa[kc][2], qa[kc][3], b2, b3);
            }
        }

        // ---- online softmax (log2 domain) ----
        float mx0 = -1e30f, mx1 = -1e30f;
#pragma unroll
        for (int nt = 0; nt < 8; nt++) {
            mx0 = fmaxf(mx0, fmaxf(S[nt][0], S[nt][1]));
            mx1 = fmaxf(mx1, fmaxf(S[nt][2], S[nt][3]));
        }
        mx0 = fmaxf(mx0, __shfl_xor_sync(0xffffffffu, mx0, 1));
        mx0 = fmaxf(mx0, __shfl_xor_sync(0xffffffffu, mx0, 2));
        mx1 = fmaxf(mx1, __shfl_xor_sync(0xffffffffu, mx1, 1));
        mx1 = fmaxf(mx1, __shfl_xor_sync(0xffffffffu, mx1, 2));

        float nm0 = fmaxf(m0, mx0), nm1 = fmaxf(m1, mx1);
        float corr0 = ex2f(m0 - nm0), corr1 = ex2f(m1 - nm1);
        m0 = nm0; m1 = nm1;

#pragma unroll
        for (int dt = 0; dt < 8; dt++) {
            O[dt][0] *= corr0; O[dt][1] *= corr0;
            O[dt][2] *= corr1; O[dt][3] *= corr1;
        }
        L[0] *= corr0; L[1] *= corr0; L[2] *= corr1; L[3] *= corr1;

        // ---- P = ex2(S - m) as packed fp16; O += P V; L += P 1 ----
#pragma unroll
        for (int c = 0; c < 4; c++) {
            uint32_t a0 = h2ex2(packh2(S[2 * c][0] - nm0,     S[2 * c][1] - nm0));
            uint32_t a1 = h2ex2(packh2(S[2 * c][2] - nm1,     S[2 * c][3] - nm1));
            uint32_t a2 = h2ex2(packh2(S[2 * c + 1][0] - nm0, S[2 * c + 1][1] - nm0));
            uint32_t a3 = h2ex2(packh2(S[2 * c + 1][2] - nm1, S[2 * c + 1][3] - nm1));
            mma_f16(L, a0, a1, a2, a3, ONE2, ONE2);
#pragma unroll
            for (int e = 0; e < 4; e++) {
                uint32_t b0, b1, b2, b3;
                uint32_t addr = Vb_a[cur] +
                    (((16 * c + (mB & 1) * 8 + rBq)) * 36 + (2 * e + (mB >> 1)) * 4) * 4;
                ldsm_x4_t(b0, b1, b2, b3, addr);
                mma_f16(O[2 * e],     a0, a1, a2, a3, b0, b1);
                mma_f16(O[2 * e + 1], a0, a1, a2, a3, b2, b3);
            }
        }

        if (more) {
            cpa_wait0();
            __syncthreads();
        }
    }

    // normalize + store (half) in concat layout [B*N, D]
    float inv0 = 1.f / L[0], inv1 = 1.f / L[2];
    __half* Ao = g_att + ((size_t)b * N_ + q0) * D_ + h * HD_;
#pragma unroll
    for (int dt = 0; dt < 8; dt++) {
        *(uint32_t*)&Ao[(size_t)(row0)     * D_ + dt * 8 + 2 * qd] = packh2(O[dt][0] * inv0, O[dt][1] * inv0);
        *(uint32_t*)&Ao[(size_t)(row0 + 8) * D_ + dt * 8 + 2 * qd] = packh2(O[dt][2] * inv1, O[dt][3] * inv1);
    }
}

// ---------------------------------------------------------------------------
// Kernel 3: output projection, cp.async double-buffered K-tiles.
// grid (12, 64). block 256 = 8 warps.
// ---------------------------------------------------------------------------
__global__ __launch_bounds__(256) void outproj_mma_kernel(
    const float* __restrict__ bo, float* __restrict__ out)
{
    extern __shared__ __align__(16) uint32_t smu[];
    uint32_t* Ab[2] = { smu, smu + 128 * 36 };
    uint32_t* Wb[2] = { smu + 2 * 128 * 36, smu + 2 * 128 * 36 + 64 * 36 };

    const int c0 = blockIdx.x * 64;
    const int r0 = blockIdx.y * 128;
    const int t  = threadIdx.x;
    const int w  = t >> 5;
    const int lane = t & 31;
    const int g  = lane >> 2;
    const int qd = lane & 3;
    const int row0 = w * 16 + g;

    const uint32_t Ab_a[2] = { (uint32_t)__cvta_generic_to_shared(Ab[0]),
                               (uint32_t)__cvta_generic_to_shared(Ab[1]) };
    const uint32_t Wb_a[2] = { (uint32_t)__cvta_generic_to_shared(Wb[0]),
                               (uint32_t)__cvta_generic_to_shared(Wb[1]) };
    const uint32_t* Ag2 = (const uint32_t*)g_att;   // row stride 384 u32

    const int mB = lane >> 3, rB = lane & 7;

    float acc[8][4];
#pragma unroll
    for (int nt = 0; nt < 8; nt++) {
        float bb0 = bo[c0 + nt * 8 + 2 * qd];
        float bb1 = bo[c0 + nt * 8 + 2 * qd + 1];
        acc[nt][0] = bb0; acc[nt][1] = bb1; acc[nt][2] = bb0; acc[nt][3] = bb1;
    }

    // prologue: issue tile 0
    {
#pragma unroll
        for (int i = t; i < 128 * 8; i += 256) {
            int r = i >> 3, c = (i & 7) << 2;
            cpa16(Ab_a[0] + (r * 36 + c) * 4, &Ag2[(size_t)(r0 + r) * 384 + c]);
        }
#pragma unroll
        for (int i = t; i < 64 * 8; i += 256) {
            int r = i >> 3, c = (i & 7) << 2;
            cpa16(Wb_a[0] + (r * 36 + c) * 4, &g_wo[(size_t)(c0 + r) * 384 + c]);
        }
        cpa_commit();
        cpa_wait0();
        __syncthreads();
    }

    for (int kt = 0; kt < D_ / 64; kt++) {
        const int cur = kt & 1;
        const bool more = (kt + 1 < D_ / 64);

        if (more) {
            const int nxt = cur ^ 1;
#pragma unroll
            for (int i = t; i < 128 * 8; i += 256) {
                int r = i >> 3, c = (i & 7) << 2;
                cpa16(Ab_a[nxt] + (r * 36 + c) * 4, &Ag2[(size_t)(r0 + r) * 384 + (kt + 1) * 32 + c]);
            }
#pragma unroll
            for (int i = t; i < 64 * 8; i += 256) {
                int r = i >> 3, c = (i & 7) << 2;
                cpa16(Wb_a[nxt] + (r * 36 + c) * 4, &g_wo[(size_t)(c0 + r) * 384 + (kt + 1) * 32 + c]);
            }
            cpa_commit();
        }

        const uint32_t aoff = ((w * 16 + (lane & 15)) * 36 + (lane >> 4) * 4) * 4;
#pragma unroll
        for (int kc = 0; kc < 4; kc++) {
            uint32_t a0, a1, a2, a3;
            ldsm_x4(a0, a1, a2, a3, Ab_a[cur] + aoff + kc * 32);
#pragma unroll
            for (int c = 0; c < 4; c++) {
                uint32_t b0, b1, b2, b3;
                uint32_t addr = Wb_a[cur] +
                    (((2 * c + (mB >> 1)) * 8 + rB) * 36 + kc * 8 + (mB & 1) * 4) * 4;
                ldsm_x4(b0, b1, b2, b3, addr);
                mma_f16(acc[2 * c],     a0, a1, a2, a3, b0, b1);
                mma_f16(acc[2 * c + 1], a0, a1, a2, a3, b2, b3);
            }
        }

        if (more) {
            cpa_wait0();
            __syncthreads();
        }
    }

#pragma unroll
    for (int nt = 0; nt < 8; nt++) {
        float2 u0 = make_float2(acc[nt][0], acc[nt][1]);
        float2 u1 = make_float2(acc[nt][2], acc[nt][3]);
        *(float2*)&out[(size_t)(r0 + row0)     * D_ + c0 + nt * 8 + 2 * qd] = u0;
        *(float2*)&out[(size_t)(r0 + row0 + 8) * D_ + c0 + nt * 8 + 2 * qd] = u1;
    }
}

// ---------------------------------------------------------------------------
extern "C" void kernel_launch(void* const* d_in, const int* in_sizes, int n_in,
                              void* d_out, int out_size)
{
    const float* x  = (const float*)d_in[0];
    const float* Wq = (const float*)d_in[1];
    const float* Wk = (const float*)d_in[2];
    const float* Wv = (const float*)d_in[3];
    const float* bq = (const float*)d_in[4];
    const float* bk = (const float*)d_in[5];
    const float* bv = (const float*)d_in[6];
    const float* Wo = (const float*)d_in[7];
    const float* bo = (const float*)d_in[8];
    float* out = (float*)d_out;

    const int qkv_smem  = (128 * 36 + 3 * 64 * 36) * 4;   // 46080
    const int attn_smem = (128 * 36 + 4 * 64 * 36) * 4;   // 55296
    const int outp_smem = (2 * 128 * 36 + 2 * 64 * 36) * 4; // 55296
    cudaFuncSetAttribute(qkv_mma_kernel, cudaFuncAttributeMaxDynamicSharedMemorySize, qkv_smem);
    cudaFuncSetAttribute(attn_mma_kernel, cudaFuncAttributeMaxDynamicSharedMemorySize, attn_smem);
    cudaFuncSetAttribute(outproj_mma_kernel, cudaFuncAttributeMaxDynamicSharedMemorySize, outp_smem);

    pack_wqkv_kernel<<<(3 * H_ * 64 * 32 + 255) / 256, 256>>>(Wq, Wk, Wv);
    pack_wo_kernel<<<(D_ * (D_ / 2) + 255) / 256, 256>>>(Wo);
    qkv_mma_kernel<<<dim3(N_ / 128, B_ * H_), 256, qkv_smem>>>(x, bq, bk, bv);
    attn_mma_kernel<<<dim3(N_ / 128, B_ * H_), 256, attn_smem>>>();
    outproj_mma_kernel<<<dim3(D_ / 64, (B_ * N_) / 128), 256, outp_smem>>>(bo, out);
}

// round 8
// speedup vs baseline: 1.3593x; 1.3593x over previous
#include <cuda_runtime.h>
#include <cuda_fp16.h>
#include <cstdint>

#define B_ 8
#define N_ 1024
#define D_ 768
#define H_ 12
#define HD_ 64

// Scratch (allocation-free rule: __device__ globals) — fp16 intermediates
__device__ __half g_q[B_ * H_ * N_ * HD_];       // pre-scaled by D^-0.5 * log2e
__device__ __half g_k[B_ * H_ * N_ * HD_];
__device__ __half g_v[B_ * H_ * N_ * HD_];
__device__ __half g_att[B_ * N_ * D_];           // concat layout [B*N, D]
__device__ uint32_t g_wqkv[3 * H_ * 64 * 32];    // [m][h][e][d2] half2, transposed
__device__ uint32_t g_wo[D_ * (D_ / 2)];         // [c][k2] half2

// ---------------------------------------------------------------------------
// helpers
// ---------------------------------------------------------------------------
__device__ __forceinline__ float ex2f(float x) {
    float y;
    asm("ex2.approx.ftz.f32 %0, %1;" : "=f"(y) : "f"(x));
    return y;
}

__device__ __forceinline__ void mma_f16(float c[4],
                                        uint32_t a0, uint32_t a1, uint32_t a2, uint32_t a3,
                                        uint32_t b0, uint32_t b1) {
    asm volatile(
        "mma.sync.aligned.m16n8k16.row.col.f32.f16.f16.f32 "
        "{%0,%1,%2,%3},{%4,%5,%6,%7},{%8,%9},{%0,%1,%2,%3};\n"
        : "+f"(c[0]), "+f"(c[1]), "+f"(c[2]), "+f"(c[3])
        : "r"(a0), "r"(a1), "r"(a2), "r"(a3), "r"(b0), "r"(b1));
}

__device__ __forceinline__ uint32_t packh2(float lo, float hi) {
    __half2 h = __floats2half2_rn(lo, hi);
    return *(uint32_t*)&h;
}

__device__ __forceinline__ void ldsm_x4(uint32_t& r0, uint32_t& r1, uint32_t& r2, uint32_t& r3,
                                        uint32_t addr) {
    asm volatile("ldmatrix.sync.aligned.m8n8.x4.shared.b16 {%0,%1,%2,%3}, [%4];"
                 : "=r"(r0), "=r"(r1), "=r"(r2), "=r"(r3) : "r"(addr));
}

__device__ __forceinline__ void ldsm_x4_t(uint32_t& r0, uint32_t& r1, uint32_t& r2, uint32_t& r3,
                                          uint32_t addr) {
    asm volatile("ldmatrix.sync.aligned.m8n8.x4.trans.shared.b16 {%0,%1,%2,%3}, [%4];"
                 : "=r"(r0), "=r"(r1), "=r"(r2), "=r"(r3) : "r"(addr));
}

// ---------------------------------------------------------------------------
// Prep kernels: pack weights to fp16 once per launch.
// ---------------------------------------------------------------------------
__global__ __launch_bounds__(256) void pack_wqkv_kernel(
    const float* __restrict__ Wq, const float* __restrict__ Wk, const float* __restrict__ Wv)
{
    int idx = blockIdx.x * 256 + threadIdx.x;          // [m][h][e][d2]
    if (idx >= 3 * H_ * 64 * 32) return;
    int d2 = idx & 31;
    int e  = (idx >> 5) & 63;
    int h  = (idx >> 11) % H_;
    int m  = idx / (H_ * 64 * 32);
    const float* W = (m == 0 ? Wq : (m == 1 ? Wk : Wv)) + h * HD_ * HD_;
    g_wqkv[idx] = packh2(W[(2 * d2) * 64 + e], W[(2 * d2 + 1) * 64 + e]);
}

__global__ __launch_bounds__(256) void pack_wo_kernel(const float* __restrict__ Wo)
{
    int idx = blockIdx.x * 256 + threadIdx.x;          // [c][k2]
    if (idx >= D_ * (D_ / 2)) return;
    float2 v = *(const float2*)&Wo[2 * idx];
    g_wo[idx] = packh2(v.x, v.y);
}

// ---------------------------------------------------------------------------
// Kernel 1: per-head QKV projection (as R6 — proven).
// ---------------------------------------------------------------------------
__global__ __launch_bounds__(256) void qkv_mma_kernel(
    const float* __restrict__ x,
    const float* __restrict__ bq, const float* __restrict__ bk, const float* __restrict__ bv)
{
    extern __shared__ __align__(16) uint32_t smu[];
    uint32_t* Xs = smu;              // [128][36]
    uint32_t* Wsm = Xs + 128 * 36;   // 3 x [64][36]

    const int bh = blockIdx.y;
    const int h  = bh % H_;
    const int b  = bh / H_;
    const int n0 = blockIdx.x * 128;
    const int t  = threadIdx.x;
    const int w  = t >> 5;
    const int lane = t & 31;
    const int g  = lane >> 2;
    const int qd = lane & 3;
    const int row0 = w * 16 + g;

    const uint32_t Xs_a = (uint32_t)__cvta_generic_to_shared(Xs);
    const uint32_t Ws_a = (uint32_t)__cvta_generic_to_shared(Wsm);

#pragma unroll
    for (int i = t; i < 128 * 8; i += 256) {
        int r = i >> 3, c8 = (i & 7) << 3;
        const float* src = &x[(b * N_ + n0 + r) * D_ + h * HD_ + c8];
        float4 v0 = *(const float4*)src;
        float4 v1 = *(const float4*)(src + 4);
        uint4 pk;
        pk.x = packh2(v0.x, v0.y); pk.y = packh2(v0.z, v0.w);
        pk.z = packh2(v1.x, v1.y); pk.w = packh2(v1.z, v1.w);
        *(uint4*)&Xs[r * 36 + ((i & 7) << 2)] = pk;
    }
#pragma unroll
    for (int i = t; i < 3 * 512; i += 256) {
        int m = i >> 9, j = i & 511;
        int r = j >> 3, c = (j & 7) << 2;
        *(uint4*)&Wsm[m * 64 * 36 + r * 36 + c] =
            *(const uint4*)&g_wqkv[(m * H_ + h) * 64 * 32 + r * 32 + c];
    }
    __syncthreads();

    uint32_t xa[4][4];
    {
        const uint32_t aoff = ((w * 16 + (lane & 15)) * 36 + (lane >> 4) * 4) * 4;
#pragma unroll
        for (int kc = 0; kc < 4; kc++)
            ldsm_x4(xa[kc][0], xa[kc][1], xa[kc][2], xa[kc][3], Xs_a + aoff + kc * 32);
    }

    const float* bm[3] = {bq, bk, bv};
    __half*      om[3] = {g_q, g_k, g_v};
    const float qscale = rsqrtf((float)D_) * 1.4426950408889634f;  // full-dim quirk * log2e

    const int mB = lane >> 3, rB = lane & 7;

#pragma unroll
    for (int m = 0; m < 3; m++) {
        const float* bias = bm[m] + h * HD_;
        float acc[8][4];
#pragma unroll
        for (int nt = 0; nt < 8; nt++) {
            float bb0 = bias[nt * 8 + 2 * qd];
            float bb1 = bias[nt * 8 + 2 * qd + 1];
            acc[nt][0] = bb0; acc[nt][1] = bb1; acc[nt][2] = bb0; acc[nt][3] = bb1;
        }

        const uint32_t wbase = Ws_a + m * 64 * 36 * 4;
#pragma unroll
        for (int kc = 0; kc < 4; kc++) {
#pragma unroll
            for (int c = 0; c < 4; c++) {
                uint32_t b0, b1, b2, b3;
                uint32_t addr = wbase +
                    (((2 * c + (mB >> 1)) * 8 + rB) * 36 + kc * 8 + (mB & 1) * 4) * 4;
                ldsm_x4(b0, b1, b2, b3, addr);
                mma_f16(acc[2 * c],     xa[kc][0], xa[kc][1], xa[kc][2], xa[kc][3], b0, b1);
                mma_f16(acc[2 * c + 1], xa[kc][0], xa[kc][1], xa[kc][2], xa[kc][3], b2, b3);
            }
        }

        const float sc = (m == 0) ? qscale : 1.0f;
        __half* o = om[m] + ((size_t)bh * N_ + n0) * HD_;
#pragma unroll
        for (int nt = 0; nt < 8; nt++) {
            *(uint32_t*)&o[(row0)     * HD_ + nt * 8 + 2 * qd] = packh2(acc[nt][0] * sc, acc[nt][1] * sc);
            *(uint32_t*)&o[(row0 + 8) * HD_ + nt * 8 + 2 * qd] = packh2(acc[nt][2] * sc, acc[nt][3] * sc);
        }
    }
}

// ---------------------------------------------------------------------------
// Kernel 2: flash attention (R6 arithmetic), double-buffered K/V smem:
// LDG register prefetch of next tile during compute, stores land in the
// idle buffer, ONE __syncthreads per tile.
// grid (8, 96). block 256 = 8 warps.
// ---------------------------------------------------------------------------
__global__ __launch_bounds__(256, 2) void attn_mma_kernel()
{
    extern __shared__ __align__(16) uint32_t smu[];
    uint32_t* Qs = smu;                                    // [128][36]
    uint32_t* Kb[2] = { Qs + 128 * 36, Qs + 128 * 36 + 2 * 64 * 36 };
    uint32_t* Vb[2] = { Qs + 128 * 36 + 64 * 36, Qs + 128 * 36 + 3 * 64 * 36 };

    const int bh = blockIdx.y;
    const int h  = bh % H_;
    const int b  = bh / H_;
    const int q0 = blockIdx.x * 128;
    const int t  = threadIdx.x;
    const int w  = t >> 5;
    const int lane = t & 31;
    const int g  = lane >> 2;
    const int qd = lane & 3;
    const int row0 = w * 16 + g;

    const uint32_t Qs_a = (uint32_t)__cvta_generic_to_shared(Qs);
    const uint32_t Kb_a[2] = { (uint32_t)__cvta_generic_to_shared(Kb[0]),
                               (uint32_t)__cvta_generic_to_shared(Kb[1]) };
    const uint32_t Vb_a[2] = { (uint32_t)__cvta_generic_to_shared(Vb[0]),
                               (uint32_t)__cvta_generic_to_shared(Vb[1]) };

    const uint32_t* Qg2 = (const uint32_t*)(g_q + ((size_t)bh * N_ + q0) * HD_);
    const uint32_t* Kg2 = (const uint32_t*)(g_k + (size_t)bh * N_ * HD_);
    const uint32_t* Vg2 = (const uint32_t*)(g_v + (size_t)bh * N_ * HD_);

    const int rA = t >> 3, cA = (t & 7) << 2;
    const int rB2 = (t + 256) >> 3, cB2 = ((t + 256) & 7) << 2;

    // Q tile
#pragma unroll
    for (int i = t; i < 128 * 8; i += 256) {
        int r = i >> 3, c = (i & 7) << 2;
        *(uint4*)&Qs[r * 36 + c] = *(const uint4*)&Qg2[r * 32 + c];
    }
    // K/V tile 0 -> buffer 0
    {
        *(uint4*)&Kb[0][rA * 36 + cA]   = *(const uint4*)&Kg2[rA * 32 + cA];
        *(uint4*)&Vb[0][rA * 36 + cA]   = *(const uint4*)&Vg2[rA * 32 + cA];
        *(uint4*)&Kb[0][rB2 * 36 + cB2] = *(const uint4*)&Kg2[rB2 * 32 + cB2];
        *(uint4*)&Vb[0][rB2 * 36 + cB2] = *(const uint4*)&Vg2[rB2 * 32 + cB2];
    }
    __syncthreads();

    // hoist Q fragments
    uint32_t qa[4][4];
    {
        const uint32_t aoff = ((w * 16 + (lane & 15)) * 36 + (lane >> 4) * 4) * 4;
#pragma unroll
        for (int kc = 0; kc < 4; kc++)
            ldsm_x4(qa[kc][0], qa[kc][1], qa[kc][2], qa[kc][3], Qs_a + aoff + kc * 32);
    }

    const int mB = lane >> 3, rBq = lane & 7;

    float O[8][4];
#pragma unroll
    for (int dt = 0; dt < 8; dt++)
#pragma unroll
        for (int j = 0; j < 4; j++) O[dt][j] = 0.f;
    float m0 = -1e30f, m1 = -1e30f, l0 = 0.f, l1 = 0.f;

    for (int kt = 0; kt < N_ / 64; kt++) {
        const int cur = kt & 1;
        const bool more = (kt + 1 < N_ / 64);

        // ---- S = Q K^T ----
        float S[8][4];
#pragma unroll
        for (int nt = 0; nt < 8; nt++)
#pragma unroll
            for (int j = 0; j < 4; j++) S[nt][j] = 0.f;

#pragma unroll
        for (int kc = 0; kc < 4; kc++) {
#pragma unroll
            for (int c = 0; c < 4; c++) {
                uint32_t b0, b1, b2, b3;
                uint32_t addr = Kb_a[cur] +
                    (((2 * c + (mB >> 1)) * 8 + rBq) * 36 + kc * 8 + (mB & 1) * 4) * 4;
                ldsm_x4(b0, b1, b2, b3, addr);
                mma_f16(S[2 * c],     qa[kc][0], qa[kc][1], qa[kc][2], qa[kc][3], b0, b1);
                mma_f16(S[2 * c + 1], qa[kc][0], qa[kc][1], qa[kc][2], qa[kc][3], b2, b3);
            }
        }

        // ---- prefetch next K/V tile into registers (overlaps softmax+PV) ----
        uint4 kp0, kp1, vp0, vp1;
        if (more) {
            const uint32_t* Kn = Kg2 + (size_t)(kt + 1) * 2048;
            const uint32_t* Vn = Vg2 + (size_t)(kt + 1) * 2048;
            kp0 = *(const uint4*)&Kn[rA * 32 + cA];
            vp0 = *(const uint4*)&Vn[rA * 32 + cA];
            kp1 = *(const uint4*)&Kn[rB2 * 32 + cB2];
            vp1 = *(const uint4*)&Vn[rB2 * 32 + cB2];
        }

        // ---- online softmax (log2 domain) ----
        float mx0 = -1e30f, mx1 = -1e30f;
#pragma unroll
        for (int nt = 0; nt < 8; nt++) {
            mx0 = fmaxf(mx0, fmaxf(S[nt][0], S[nt][1]));
            mx1 = fmaxf(mx1, fmaxf(S[nt][2], S[nt][3]));
        }
        mx0 = fmaxf(mx0, __shfl_xor_sync(0xffffffffu, mx0, 1));
        mx0 = fmaxf(mx0, __shfl_xor_sync(0xffffffffu, mx0, 2));
        mx1 = fmaxf(mx1, __shfl_xor_sync(0xffffffffu, mx1, 1));
        mx1 = fmaxf(mx1, __shfl_xor_sync(0xffffffffu, mx1, 2));

        float nm0 = fmaxf(m0, mx0), nm1 = fmaxf(m1, mx1);
        float corr0 = ex2f(m0 - nm0), corr1 = ex2f(m1 - nm1);
        m0 = nm0; m1 = nm1;

        float s0 = 0.f, s1 = 0.f;
#pragma unroll
        for (int nt = 0; nt < 8; nt++) {
            S[nt][0] = ex2f(S[nt][0] - nm0);
            S[nt][1] = ex2f(S[nt][1] - nm0);
            S[nt][2] = ex2f(S[nt][2] - nm1);
            S[nt][3] = ex2f(S[nt][3] - nm1);
            s0 += S[nt][0] + S[nt][1];
            s1 += S[nt][2] + S[nt][3];
        }
        s0 += __shfl_xor_sync(0xffffffffu, s0, 1);
        s0 += __shfl_xor_sync(0xffffffffu, s0, 2);
        s1 += __shfl_xor_sync(0xffffffffu, s1, 1);
        s1 += __shfl_xor_sync(0xffffffffu, s1, 2);
        l0 = l0 * corr0 + s0;
        l1 = l1 * corr1 + s1;

#pragma unroll
        for (int dt = 0; dt < 8; dt++) {
            O[dt][0] *= corr0; O[dt][1] *= corr0;
            O[dt][2] *= corr1; O[dt][3] *= corr1;
        }

        // ---- O += P V (P register-packed; V b-frags via ldmatrix.trans) ----
#pragma unroll
        for (int c = 0; c < 4; c++) {
            uint32_t a0 = packh2(S[2 * c][0],     S[2 * c][1]);
            uint32_t a1 = packh2(S[2 * c][2],     S[2 * c][3]);
            uint32_t a2 = packh2(S[2 * c + 1][0], S[2 * c + 1][1]);
            uint32_t a3 = packh2(S[2 * c + 1][2], S[2 * c + 1][3]);
#pragma unroll
            for (int e = 0; e < 4; e++) {
                uint32_t b0, b1, b2, b3;
                uint32_t addr = Vb_a[cur] +
                    (((16 * c + (mB & 1) * 8 + rBq)) * 36 + (2 * e + (mB >> 1)) * 4) * 4;
                ldsm_x4_t(b0, b1, b2, b3, addr);
                mma_f16(O[2 * e],     a0, a1, a2, a3, b0, b1);
                mma_f16(O[2 * e + 1], a0, a1, a2, a3, b2, b3);
            }
        }

        // ---- commit prefetched tile to the IDLE buffer, one barrier ----
        if (more) {
            const int nxt = cur ^ 1;
            *(uint4*)&Kb[nxt][rA * 36 + cA]   = kp0;
            *(uint4*)&Vb[nxt][rA * 36 + cA]   = vp0;
            *(uint4*)&Kb[nxt][rB2 * 36 + cB2] = kp1;
            *(uint4*)&Vb[nxt][rB2 * 36 + cB2] = vp1;
            __syncthreads();
        }
    }

    // normalize + store (half) in concat layout [B*N, D]
    float inv0 = 1.f / l0, inv1 = 1.f / l1;
    __half* Ao = g_att + ((size_t)b * N_ + q0) * D_ + h * HD_;
#pragma unroll
    for (int dt = 0; dt < 8; dt++) {
        *(uint32_t*)&Ao[(size_t)(row0)     * D_ + dt * 8 + 2 * qd] = packh2(O[dt][0] * inv0, O[dt][1] * inv0);
        *(uint32_t*)&Ao[(size_t)(row0 + 8) * D_ + dt * 8 + 2 * qd] = packh2(O[dt][2] * inv1, O[dt][3] * inv1);
    }
}

// ---------------------------------------------------------------------------
// Kernel 3: output projection, double-buffered smem + LDG register prefetch,
// one barrier per k-tile. grid (12, 64). block 256 = 8 warps.
// ---------------------------------------------------------------------------
__global__ __launch_bounds__(256) void outproj_mma_kernel(
    const float* __restrict__ bo, float* __restrict__ out)
{
    extern __shared__ __align__(16) uint32_t smu[];
    uint32_t* Ab[2] = { smu, smu + 128 * 36 };
    uint32_t* Wb[2] = { smu + 2 * 128 * 36, smu + 2 * 128 * 36 + 64 * 36 };

    const int c0 = blockIdx.x * 64;
    const int r0 = blockIdx.y * 128;
    const int t  = threadIdx.x;
    const int w  = t >> 5;
    const int lane = t & 31;
    const int g  = lane >> 2;
    const int qd = lane & 3;
    const int row0 = w * 16 + g;

    const uint32_t Ab_a[2] = { (uint32_t)__cvta_generic_to_shared(Ab[0]),
                               (uint32_t)__cvta_generic_to_shared(Ab[1]) };
    const uint32_t Wb_a[2] = { (uint32_t)__cvta_generic_to_shared(Wb[0]),
                               (uint32_t)__cvta_generic_to_shared(Wb[1]) };
    const uint32_t* Ag2 = (const uint32_t*)g_att;   // row stride 384 u32

    const int mB = lane >> 3, rB = lane & 7;
    // per-thread copy slots: A tile 4 chunks, W tile 2 chunks
    const int rA0 = t >> 3,          cA0 = (t & 7) << 2;     // + 256,512,768
    const int rW0 = t >> 3,          cW0 = (t & 7) << 2;     // + 256

    float acc[8][4];
#pragma unroll
    for (int nt = 0; nt < 8; nt++) {
        float bb0 = bo[c0 + nt * 8 + 2 * qd];
        float bb1 = bo[c0 + nt * 8 + 2 * qd + 1];
        acc[nt][0] = bb0; acc[nt][1] = bb1; acc[nt][2] = bb0; acc[nt][3] = bb1;
    }

    // tile 0 -> buffer 0
#pragma unroll
    for (int u = 0; u < 4; u++) {
        int i = t + u * 256;
        int r = i >> 3, c = (i & 7) << 2;
        *(uint4*)&Ab[0][r * 36 + c] = *(const uint4*)&Ag2[(size_t)(r0 + r) * 384 + c];
    }
#pragma unroll
    for (int u = 0; u < 2; u++) {
        int i = t + u * 256;
        int r = i >> 3, c = (i & 7) << 2;
        *(uint4*)&Wb[0][r * 36 + c] = *(const uint4*)&g_wo[(size_t)(c0 + r) * 384 + c];
    }
    __syncthreads();

    for (int kt = 0; kt < D_ / 64; kt++) {
        const int cur = kt & 1;
        const bool more = (kt + 1 < D_ / 64);

        // prefetch next tile into registers
        uint4 ap[4], wp[2];
        if (more) {
#pragma unroll
            for (int u = 0; u < 4; u++) {
                int i = t + u * 256;
                int r = i >> 3, c = (i & 7) << 2;
                ap[u] = *(const uint4*)&Ag2[(size_t)(r0 + r) * 384 + (kt + 1) * 32 + c];
            }
#pragma unroll
            for (int u = 0; u < 2; u++) {
                int i = t + u * 256;
                int r = i >> 3, c = (i & 7) << 2;
                wp[u] = *(const uint4*)&g_wo[(size_t)(c0 + r) * 384 + (kt + 1) * 32 + c];
            }
        }

        const uint32_t aoff = ((w * 16 + (lane & 15)) * 36 + (lane >> 4) * 4) * 4;
#pragma unroll
        for (int kc = 0; kc < 4; kc++) {
            uint32_t a0, a1, a2, a3;
            ldsm_x4(a0, a1, a2, a3, Ab_a[cur] + aoff + kc * 32);
#pragma unroll
            for (int c = 0; c < 4; c++) {
                uint32_t b0, b1, b2, b3;
                uint32_t addr = Wb_a[cur] +
                    (((2 * c + (mB >> 1)) * 8 + rB) * 36 + kc * 8 + (mB & 1) * 4) * 4;
                ldsm_x4(b0, b1, b2, b3, addr);
                mma_f16(acc[2 * c],     a0, a1, a2, a3, b0, b1);
                mma_f16(acc[2 * c + 1], a0, a1, a2, a3, b2, b3);
            }
        }

        if (more) {
            const int nxt = cur ^ 1;
#pragma unroll
            for (int u = 0; u < 4; u++) {
                int i = t + u * 256;
                int r = i >> 3, c = (i & 7) << 2;
                *(uint4*)&Ab[nxt][r * 36 + c] = ap[u];
            }
#pragma unroll
            for (int u = 0; u < 2; u++) {
                int i = t + u * 256;
                int r = i >> 3, c = (i & 7) << 2;
                *(uint4*)&Wb[nxt][r * 36 + c] = wp[u];
            }
            __syncthreads();
        }
    }

#pragma unroll
    for (int nt = 0; nt < 8; nt++) {
        float2 u0 = make_float2(acc[nt][0], acc[nt][1]);
        float2 u1 = make_float2(acc[nt][2], acc[nt][3]);
        *(float2*)&out[(size_t)(r0 + row0)     * D_ + c0 + nt * 8 + 2 * qd] = u0;
        *(float2*)&out[(size_t)(r0 + row0 + 8) * D_ + c0 + nt * 8 + 2 * qd] = u1;
    }
}

// ---------------------------------------------------------------------------
extern "C" void kernel_launch(void* const* d_in, const int* in_sizes, int n_in,
                              void* d_out, int out_size)
{
    const float* x  = (const float*)d_in[0];
    const float* Wq = (const float*)d_in[1];
    const float* Wk = (const float*)d_in[2];
    const float* Wv = (const float*)d_in[3];
    const float* bq = (const float*)d_in[4];
    const float* bk = (const float*)d_in[5];
    const float* bv = (const float*)d_in[6];
    const float* Wo = (const float*)d_in[7];
    const float* bo = (const float*)d_in[8];
    float* out = (float*)d_out;

    const int qkv_smem  = (128 * 36 + 3 * 64 * 36) * 4;     // 46080
    const int attn_smem = (128 * 36 + 4 * 64 * 36) * 4;     // 55296
    const int outp_smem = (2 * 128 * 36 + 2 * 64 * 36) * 4; // 55296
    cudaFuncSetAttribute(qkv_mma_kernel, cudaFuncAttributeMaxDynamicSharedMemorySize, qkv_smem);
    cudaFuncSetAttribute(attn_mma_kernel, cudaFuncAttributeMaxDynamicSharedMemorySize, attn_smem);
    cudaFuncSetAttribute(outproj_mma_kernel, cudaFuncAttributeMaxDynamicSharedMemorySize, outp_smem);

    pack_wqkv_kernel<<<(3 * H_ * 64 * 32 + 255) / 256, 256>>>(Wq, Wk, Wv);
    pack_wo_kernel<<<(D_ * (D_ / 2) + 255) / 256, 256>>>(Wo);
    qkv_mma_kernel<<<dim3(N_ / 128, B_ * H_), 256, qkv_smem>>>(x, bq, bk, bv);
    attn_mma_kernel<<<dim3(N_ / 128, B_ * H_), 256, attn_smem>>>();
    outproj_mma_kernel<<<dim3(D_ / 64, (B_ * N_) / 128), 256, outp_smem>>>(bo, out);
}

// round 9
// speedup vs baseline: 1.4488x; 1.0658x over previous
#include <cuda_runtime.h>
#include <cuda_fp16.h>
#include <cstdint>

#define B_ 8
#define N_ 1024
#define D_ 768
#define H_ 12
#define HD_ 64

// Scratch (allocation-free rule: __device__ globals) — fp16 intermediates
__device__ __half g_q[B_ * H_ * N_ * HD_];       // pre-scaled by D^-0.5 * log2e
__device__ __half g_k[B_ * H_ * N_ * HD_];
__device__ __half g_v[B_ * H_ * N_ * HD_];
__device__ __half g_att[B_ * N_ * D_];           // concat layout [B*N, D]
__device__ uint32_t g_wqkv[3 * H_ * 64 * 32];    // [m][h][e][d2] half2, transposed
__device__ uint32_t g_wo[D_ * (D_ / 2)];         // [c][k2] half2

// ---------------------------------------------------------------------------
// helpers
// ---------------------------------------------------------------------------
__device__ __forceinline__ float ex2f(float x) {
    float y;
    asm("ex2.approx.ftz.f32 %0, %1;" : "=f"(y) : "f"(x));
    return y;
}

__device__ __forceinline__ uint32_t h2ex2(uint32_t a) {
    uint32_t d;
    asm("ex2.approx.f16x2 %0, %1;" : "=r"(d) : "r"(a));
    return d;
}

__device__ __forceinline__ void mma_f16(float c[4],
                                        uint32_t a0, uint32_t a1, uint32_t a2, uint32_t a3,
                                        uint32_t b0, uint32_t b1) {
    asm volatile(
        "mma.sync.aligned.m16n8k16.row.col.f32.f16.f16.f32 "
        "{%0,%1,%2,%3},{%4,%5,%6,%7},{%8,%9},{%0,%1,%2,%3};\n"
        : "+f"(c[0]), "+f"(c[1]), "+f"(c[2]), "+f"(c[3])
        : "r"(a0), "r"(a1), "r"(a2), "r"(a3), "r"(b0), "r"(b1));
}

__device__ __forceinline__ uint32_t packh2(float lo, float hi) {
    __half2 h = __floats2half2_rn(lo, hi);
    return *(uint32_t*)&h;
}

__device__ __forceinline__ void ldsm_x4(uint32_t& r0, uint32_t& r1, uint32_t& r2, uint32_t& r3,
                                        uint32_t addr) {
    asm volatile("ldmatrix.sync.aligned.m8n8.x4.shared.b16 {%0,%1,%2,%3}, [%4];"
                 : "=r"(r0), "=r"(r1), "=r"(r2), "=r"(r3) : "r"(addr));
}

__device__ __forceinline__ void ldsm_x4_t(uint32_t& r0, uint32_t& r1, uint32_t& r2, uint32_t& r3,
                                          uint32_t addr) {
    asm volatile("ldmatrix.sync.aligned.m8n8.x4.trans.shared.b16 {%0,%1,%2,%3}, [%4];"
                 : "=r"(r0), "=r"(r1), "=r"(r2), "=r"(r3) : "r"(addr));
}

// ---------------------------------------------------------------------------
// Prep kernels: pack weights to fp16 once per launch.
// ---------------------------------------------------------------------------
__global__ __launch_bounds__(256) void pack_wqkv_kernel(
    const float* __restrict__ Wq, const float* __restrict__ Wk, const float* __restrict__ Wv)
{
    int idx = blockIdx.x * 256 + threadIdx.x;          // [m][h][e][d2]
    if (idx >= 3 * H_ * 64 * 32) return;
    int d2 = idx & 31;
    int e  = (idx >> 5) & 63;
    int h  = (idx >> 11) % H_;
    int m  = idx / (H_ * 64 * 32);
    const float* W = (m == 0 ? Wq : (m == 1 ? Wk : Wv)) + h * HD_ * HD_;
    g_wqkv[idx] = packh2(W[(2 * d2) * 64 + e], W[(2 * d2 + 1) * 64 + e]);
}

__global__ __launch_bounds__(256) void pack_wo_kernel(const float* __restrict__ Wo)
{
    int idx = blockIdx.x * 256 + threadIdx.x;          // [c][k2]
    if (idx >= D_ * (D_ / 2)) return;
    float2 v = *(const float2*)&Wo[2 * idx];
    g_wo[idx] = packh2(v.x, v.y);
}

// ---------------------------------------------------------------------------
// Kernel 1: per-head QKV projection (as R6 — proven).
// ---------------------------------------------------------------------------
__global__ __launch_bounds__(256) void qkv_mma_kernel(
    const float* __restrict__ x,
    const float* __restrict__ bq, const float* __restrict__ bk, const float* __restrict__ bv)
{
    extern __shared__ __align__(16) uint32_t smu[];
    uint32_t* Xs = smu;              // [128][36]
    uint32_t* Wsm = Xs + 128 * 36;   // 3 x [64][36]

    const int bh = blockIdx.y;
    const int h  = bh % H_;
    const int b  = bh / H_;
    const int n0 = blockIdx.x * 128;
    const int t  = threadIdx.x;
    const int w  = t >> 5;
    const int lane = t & 31;
    const int g  = lane >> 2;
    const int qd = lane & 3;
    const int row0 = w * 16 + g;

    const uint32_t Xs_a = (uint32_t)__cvta_generic_to_shared(Xs);
    const uint32_t Ws_a = (uint32_t)__cvta_generic_to_shared(Wsm);

#pragma unroll
    for (int i = t; i < 128 * 8; i += 256) {
        int r = i >> 3, c8 = (i & 7) << 3;
        const float* src = &x[(b * N_ + n0 + r) * D_ + h * HD_ + c8];
        float4 v0 = *(const float4*)src;
        float4 v1 = *(const float4*)(src + 4);
        uint4 pk;
        pk.x = packh2(v0.x, v0.y); pk.y = packh2(v0.z, v0.w);
        pk.z = packh2(v1.x, v1.y); pk.w = packh2(v1.z, v1.w);
        *(uint4*)&Xs[r * 36 + ((i & 7) << 2)] = pk;
    }
#pragma unroll
    for (int i = t; i < 3 * 512; i += 256) {
        int m = i >> 9, j = i & 511;
        int r = j >> 3, c = (j & 7) << 2;
        *(uint4*)&Wsm[m * 64 * 36 + r * 36 + c] =
            *(const uint4*)&g_wqkv[(m * H_ + h) * 64 * 32 + r * 32 + c];
    }
    __syncthreads();

    uint32_t xa[4][4];
    {
        const uint32_t aoff = ((w * 16 + (lane & 15)) * 36 + (lane >> 4) * 4) * 4;
#pragma unroll
        for (int kc = 0; kc < 4; kc++)
            ldsm_x4(xa[kc][0], xa[kc][1], xa[kc][2], xa[kc][3], Xs_a + aoff + kc * 32);
    }

    const float* bm[3] = {bq, bk, bv};
    __half*      om[3] = {g_q, g_k, g_v};
    const float qscale = rsqrtf((float)D_) * 1.4426950408889634f;  // full-dim quirk * log2e

    const int mB = lane >> 3, rB = lane & 7;

#pragma unroll
    for (int m = 0; m < 3; m++) {
        const float* bias = bm[m] + h * HD_;
        float acc[8][4];
#pragma unroll
        for (int nt = 0; nt < 8; nt++) {
            float bb0 = bias[nt * 8 + 2 * qd];
            float bb1 = bias[nt * 8 + 2 * qd + 1];
            acc[nt][0] = bb0; acc[nt][1] = bb1; acc[nt][2] = bb0; acc[nt][3] = bb1;
        }

        const uint32_t wbase = Ws_a + m * 64 * 36 * 4;
#pragma unroll
        for (int kc = 0; kc < 4; kc++) {
#pragma unroll
            for (int c = 0; c < 4; c++) {
                uint32_t b0, b1, b2, b3;
                uint32_t addr = wbase +
                    (((2 * c + (mB >> 1)) * 8 + rB) * 36 + kc * 8 + (mB & 1) * 4) * 4;
                ldsm_x4(b0, b1, b2, b3, addr);
                mma_f16(acc[2 * c],     xa[kc][0], xa[kc][1], xa[kc][2], xa[kc][3], b0, b1);
                mma_f16(acc[2 * c + 1], xa[kc][0], xa[kc][1], xa[kc][2], xa[kc][3], b2, b3);
            }
        }

        const float sc = (m == 0) ? qscale : 1.0f;
        __half* o = om[m] + ((size_t)bh * N_ + n0) * HD_;
#pragma unroll
        for (int nt = 0; nt < 8; nt++) {
            *(uint32_t*)&o[(row0)     * HD_ + nt * 8 + 2 * qd] = packh2(acc[nt][0] * sc, acc[nt][1] * sc);
            *(uint32_t*)&o[(row0 + 8) * HD_ + nt * 8 + 2 * qd] = packh2(acc[nt][2] * sc, acc[nt][3] * sc);
        }
    }
}

// ---------------------------------------------------------------------------
// Kernel 2: flash attention — R6 memory structure (single K/V buffer,
// register prefetch, 2 syncs/tile) with h2ex2 softmax + ones-MMA row-sum.
// grid (8, 96). block 256 = 8 warps.
// ---------------------------------------------------------------------------
__global__ __launch_bounds__(256, 2) void attn_mma_kernel()
{
    extern __shared__ __align__(16) uint32_t smu[];
    uint32_t* Qs = smu;              // [128][36]
    uint32_t* Ks = Qs + 128 * 36;    // [64][36]
    uint32_t* Vs = Ks + 64 * 36;     // [64][36] natural layout

    const int bh = blockIdx.y;
    const int h  = bh % H_;
    const int b  = bh / H_;
    const int q0 = blockIdx.x * 128;
    const int t  = threadIdx.x;
    const int w  = t >> 5;
    const int lane = t & 31;
    const int g  = lane >> 2;
    const int qd = lane & 3;
    const int row0 = w * 16 + g;
    const uint32_t ONE2 = 0x3C003C00u;   // half2(1,1)

    const uint32_t Qs_a = (uint32_t)__cvta_generic_to_shared(Qs);
    const uint32_t Ks_a = (uint32_t)__cvta_generic_to_shared(Ks);
    const uint32_t Vs_a = (uint32_t)__cvta_generic_to_shared(Vs);

    const uint32_t* Qg2 = (const uint32_t*)(g_q + ((size_t)bh * N_ + q0) * HD_);
    const uint32_t* Kg2 = (const uint32_t*)(g_k + (size_t)bh * N_ * HD_);
    const uint32_t* Vg2 = (const uint32_t*)(g_v + (size_t)bh * N_ * HD_);

    const int rA = t >> 3, cA = (t & 7) << 2;
    // Q tile
#pragma unroll
    for (int i = t; i < 128 * 8; i += 256) {
        int r = i >> 3, c = (i & 7) << 2;
        *(uint4*)&Qs[r * 36 + c] = *(const uint4*)&Qg2[r * 32 + c];
    }
    // K/V tile 0
    {
        *(uint4*)&Ks[rA * 36 + cA] = *(const uint4*)&Kg2[rA * 32 + cA];
        *(uint4*)&Vs[rA * 36 + cA] = *(const uint4*)&Vg2[rA * 32 + cA];
        int u = t + 256;
        int r1 = u >> 3, c1 = (u & 7) << 2;
        *(uint4*)&Ks[r1 * 36 + c1] = *(const uint4*)&Kg2[r1 * 32 + c1];
        *(uint4*)&Vs[r1 * 36 + c1] = *(const uint4*)&Vg2[r1 * 32 + c1];
    }
    __syncthreads();

    // hoist Q fragments
    uint32_t qa[4][4];
    {
        const uint32_t aoff = ((w * 16 + (lane & 15)) * 36 + (lane >> 4) * 4) * 4;
#pragma unroll
        for (int kc = 0; kc < 4; kc++)
            ldsm_x4(qa[kc][0], qa[kc][1], qa[kc][2], qa[kc][3], Qs_a + aoff + kc * 32);
    }

    const int mB = lane >> 3, rBq = lane & 7;

    float O[8][4];
#pragma unroll
    for (int dt = 0; dt < 8; dt++)
#pragma unroll
        for (int j = 0; j < 4; j++) O[dt][j] = 0.f;
    float L[4] = {0.f, 0.f, 0.f, 0.f};
    float m0 = -1e30f, m1 = -1e30f;

    for (int kt = 0; kt < N_ / 64; kt++) {
        // ---- S = Q K^T ----
        float S[8][4];
#pragma unroll
        for (int nt = 0; nt < 8; nt++)
#pragma unroll
            for (int j = 0; j < 4; j++) S[nt][j] = 0.f;

#pragma unroll
        for (int kc = 0; kc < 4; kc++) {
#pragma unroll
            for (int c = 0; c < 4; c++) {
                uint32_t b0, b1, b2, b3;
                uint32_t addr = Ks_a +
                    (((2 * c + (mB >> 1)) * 8 + rBq) * 36 + kc * 8 + (mB & 1) * 4) * 4;
                ldsm_x4(b0, b1, b2, b3, addr);
                mma_f16(S[2 * c],     qa[kc][0], qa[kc][1], qa[kc][2], qa[kc][3], b0, b1);
                mma_f16(S[2 * c + 1], qa[kc][0], qa[kc][1], qa[kc][2], qa[kc][3], b2, b3);
            }
        }

        // ---- prefetch next K/V tile into registers (overlaps softmax+PV) ----
        uint4 kp0, kp1, vp0, vp1;
        const bool more = (kt + 1 < N_ / 64);
        if (more) {
            const uint32_t* Kn = Kg2 + (size_t)(kt + 1) * 2048;
            const uint32_t* Vn = Vg2 + (size_t)(kt + 1) * 2048;
            kp0 = *(const uint4*)&Kn[rA * 32 + cA];
            vp0 = *(const uint4*)&Vn[rA * 32 + cA];
            int u = t + 256;
            int r1 = u >> 3, c1 = (u & 7) << 2;
            kp1 = *(const uint4*)&Kn[r1 * 32 + c1];
            vp1 = *(const uint4*)&Vn[r1 * 32 + c1];
        }

        // ---- online softmax: max-reduce (fp32), then h2ex2 packed P ----
        float mx0 = -1e30f, mx1 = -1e30f;
#pragma unroll
        for (int nt = 0; nt < 8; nt++) {
            mx0 = fmaxf(mx0, fmaxf(S[nt][0], S[nt][1]));
            mx1 = fmaxf(mx1, fmaxf(S[nt][2], S[nt][3]));
        }
        mx0 = fmaxf(mx0, __shfl_xor_sync(0xffffffffu, mx0, 1));
        mx0 = fmaxf(mx0, __shfl_xor_sync(0xffffffffu, mx0, 2));
        mx1 = fmaxf(mx1, __shfl_xor_sync(0xffffffffu, mx1, 1));
        mx1 = fmaxf(mx1, __shfl_xor_sync(0xffffffffu, mx1, 2));

        float nm0 = fmaxf(m0, mx0), nm1 = fmaxf(m1, mx1);
        float corr0 = ex2f(m0 - nm0), corr1 = ex2f(m1 - nm1);
        m0 = nm0; m1 = nm1;

#pragma unroll
        for (int dt = 0; dt < 8; dt++) {
            O[dt][0] *= corr0; O[dt][1] *= corr0;
            O[dt][2] *= corr1; O[dt][3] *= corr1;
        }
        L[0] *= corr0; L[1] *= corr0; L[2] *= corr1; L[3] *= corr1;

        // ---- P = ex2(S - m) packed fp16; L += P*1 (MMA); O += P V ----
#pragma unroll
        for (int c = 0; c < 4; c++) {
            uint32_t a0 = h2ex2(packh2(S[2 * c][0] - nm0,     S[2 * c][1] - nm0));
            uint32_t a1 = h2ex2(packh2(S[2 * c][2] - nm1,     S[2 * c][3] - nm1));
            uint32_t a2 = h2ex2(packh2(S[2 * c + 1][0] - nm0, S[2 * c + 1][1] - nm0));
            uint32_t a3 = h2ex2(packh2(S[2 * c + 1][2] - nm1, S[2 * c + 1][3] - nm1));
            mma_f16(L, a0, a1, a2, a3, ONE2, ONE2);
#pragma unroll
            for (int e = 0; e < 4; e++) {
                uint32_t b0, b1, b2, b3;
                uint32_t addr = Vs_a +
                    (((16 * c + (mB & 1) * 8 + rBq)) * 36 + (2 * e + (mB >> 1)) * 4) * 4;
                ldsm_x4_t(b0, b1, b2, b3, addr);
                mma_f16(O[2 * e],     a0, a1, a2, a3, b0, b1);
                mma_f16(O[2 * e + 1], a0, a1, a2, a3, b2, b3);
            }
        }

        // ---- commit prefetched tile ----
        if (more) {
            __syncthreads();
            *(uint4*)&Ks[rA * 36 + cA] = kp0;
            *(uint4*)&Vs[rA * 36 + cA] = vp0;
            int u = t + 256;
            int r1 = u >> 3, c1 = (u & 7) << 2;
            *(uint4*)&Ks[r1 * 36 + c1] = kp1;
            *(uint4*)&Vs[r1 * 36 + c1] = vp1;
            __syncthreads();
        }
    }

    // normalize + store (half) in concat layout [B*N, D]
    float inv0 = 1.f / L[0], inv1 = 1.f / L[2];
    __half* Ao = g_att + ((size_t)b * N_ + q0) * D_ + h * HD_;
#pragma unroll
    for (int dt = 0; dt < 8; dt++) {
        *(uint32_t*)&Ao[(size_t)(row0)     * D_ + dt * 8 + 2 * qd] = packh2(O[dt][0] * inv0, O[dt][1] * inv0);
        *(uint32_t*)&Ao[(size_t)(row0 + 8) * D_ + dt * 8 + 2 * qd] = packh2(O[dt][2] * inv1, O[dt][3] * inv1);
    }
}

// ---------------------------------------------------------------------------
// Kernel 3: output projection (as R6 — proven).
// grid (12, 64). block 256 = 8 warps.
// ---------------------------------------------------------------------------
__global__ __launch_bounds__(256) void outproj_mma_kernel(
    const float* __restrict__ bo, float* __restrict__ out)
{
    extern __shared__ __align__(16) uint32_t smu[];
    uint32_t* As = smu;              // [128][36]
    uint32_t* Ws = As + 128 * 36;    // [64][36]

    const int c0 = blockIdx.x * 64;
    const int r0 = blockIdx.y * 128;
    const int t  = threadIdx.x;
    const int w  = t >> 5;
    const int lane = t & 31;
    const int g  = lane >> 2;
    const int qd = lane & 3;
    const int row0 = w * 16 + g;

    const uint32_t As_a = (uint32_t)__cvta_generic_to_shared(As);
    const uint32_t Ws_a = (uint32_t)__cvta_generic_to_shared(Ws);
    const uint32_t* Ag2 = (const uint32_t*)g_att;   // row stride 384 u32

    const int mB = lane >> 3, rB = lane & 7;

    float acc[8][4];
#pragma unroll
    for (int nt = 0; nt < 8; nt++) {
        float bb0 = bo[c0 + nt * 8 + 2 * qd];
        float bb1 = bo[c0 + nt * 8 + 2 * qd + 1];
        acc[nt][0] = bb0; acc[nt][1] = bb1; acc[nt][2] = bb0; acc[nt][3] = bb1;
    }

    for (int kt = 0; kt < D_ / 64; kt++) {
        __syncthreads();
#pragma unroll
        for (int i = t; i < 128 * 8; i += 256) {
            int r = i >> 3, c = (i & 7) << 2;
            *(uint4*)&As[r * 36 + c] = *(const uint4*)&Ag2[(size_t)(r0 + r) * 384 + kt * 32 + c];
        }
#pragma unroll
        for (int i = t; i < 64 * 8; i += 256) {
            int r = i >> 3, c = (i & 7) << 2;
            *(uint4*)&Ws[r * 36 + c] = *(const uint4*)&g_wo[(size_t)(c0 + r) * 384 + kt * 32 + c];
        }
        __syncthreads();

        const uint32_t aoff = ((w * 16 + (lane & 15)) * 36 + (lane >> 4) * 4) * 4;
#pragma unroll
        for (int kc = 0; kc < 4; kc++) {
            uint32_t a0, a1, a2, a3;
            ldsm_x4(a0, a1, a2, a3, As_a + aoff + kc * 32);
#pragma unroll
            for (int c = 0; c < 4; c++) {
                uint32_t b0, b1, b2, b3;
                uint32_t addr = Ws_a +
                    (((2 * c + (mB >> 1)) * 8 + rB) * 36 + kc * 8 + (mB & 1) * 4) * 4;
                ldsm_x4(b0, b1, b2, b3, addr);
                mma_f16(acc[2 * c],     a0, a1, a2, a3, b0, b1);
                mma_f16(acc[2 * c + 1], a0, a1, a2, a3, b2, b3);
            }
        }
    }

#pragma unroll
    for (int nt = 0; nt < 8; nt++) {
        float2 u0 = make_float2(acc[nt][0], acc[nt][1]);
        float2 u1 = make_float2(acc[nt][2], acc[nt][3]);
        *(float2*)&out[(size_t)(r0 + row0)     * D_ + c0 + nt * 8 + 2 * qd] = u0;
        *(float2*)&out[(size_t)(r0 + row0 + 8) * D_ + c0 + nt * 8 + 2 * qd] = u1;
    }
}

// ---------------------------------------------------------------------------
extern "C" void kernel_launch(void* const* d_in, const int* in_sizes, int n_in,
                              void* d_out, int out_size)
{
    const float* x  = (const float*)d_in[0];
    const float* Wq = (const float*)d_in[1];
    const float* Wk = (const float*)d_in[2];
    const float* Wv = (const float*)d_in[3];
    const float* bq = (const float*)d_in[4];
    const float* bk = (const float*)d_in[5];
    const float* bv = (const float*)d_in[6];
    const float* Wo = (const float*)d_in[7];
    const float* bo = (const float*)d_in[8];
    float* out = (float*)d_out;

    const int qkv_smem  = (128 * 36 + 3 * 64 * 36) * 4;   // 46080
    const int attn_smem = (128 * 36 + 2 * 64 * 36) * 4;   // 36864
    const int outp_smem = (128 * 36 + 64 * 36) * 4;       // 27648
    cudaFuncSetAttribute(qkv_mma_kernel, cudaFuncAttributeMaxDynamicSharedMemorySize, qkv_smem);
    cudaFuncSetAttribute(attn_mma_kernel, cudaFuncAttributeMaxDynamicSharedMemorySize, attn_smem);
    cudaFuncSetAttribute(outproj_mma_kernel, cudaFuncAttributeMaxDynamicSharedMemorySize, outp_smem);

    pack_wqkv_kernel<<<(3 * H_ * 64 * 32 + 255) / 256, 256>>>(Wq, Wk, Wv);
    pack_wo_kernel<<<(D_ * (D_ / 2) + 255) / 256, 256>>>(Wo);
    qkv_mma_kernel<<<dim3(N_ / 128, B_ * H_), 256, qkv_smem>>>(x, bq, bk, bv);
    attn_mma_kernel<<<dim3(N_ / 128, B_ * H_), 256, attn_smem>>>();
    outproj_mma_kernel<<<dim3(D_ / 64, (B_ * N_) / 128), 256, outp_smem>>>(bo, out);
}